// round 3
// baseline (speedup 1.0000x reference)
#include <cuda_runtime.h>
#include <cuda_bf16.h>
#include <cstdint>

// Problem constants
#define BS       32
#define SEQ_LEN  4096
#define HIDDEN   1024
#define QUARTERS 4          // CTAs per batch row
#define TPB      256        // threads per CTA

__device__ __forceinline__ unsigned rotl32(unsigned x, int r) {
    return (x << r) | (x >> (32 - r));
}

// grid = (QUARTERS, BS), block = TPB.
// CTA (q, b): computes batch-b prefix redundantly, handles emb [q*256, q*256+256).
__global__ void __launch_bounds__(TPB, 1)
condensed_embracement_kernel(const float* __restrict__ tokens,
                             const int*   __restrict__ mask,
                             float*       __restrict__ out) {
    const int b = blockIdx.y;
    const int q = blockIdx.x;
    const int t = threadIdx.x;

    // ---- Phase 1: prefix = sum of mask row (mask is 1^L 0^(S-L)) ----
    // 4096 ints / 256 threads = 4 int4 per thread, coalesced, MLP=4.
    const int4* m4 = reinterpret_cast<const int4*>(mask + (size_t)b * SEQ_LEN);
    int s = 0;
    #pragma unroll
    for (int i = 0; i < 4; i++) {
        int4 v = m4[t + i * TPB];
        s += v.x + v.y + v.z + v.w;
    }

    // Warp-level: single REDUX.SUM instead of shfl tree.
    s = __reduce_add_sync(0xffffffffu, s);

    // Cross-warp: 8 partials; ONE barrier, then every thread sums all 8.
    __shared__ int wsum[TPB / 32];
    if ((t & 31) == 0) wsum[t >> 5] = s;
    __syncthreads();
    int prefix = 0;
    #pragma unroll
    for (int w = 0; w < TPB / 32; w++) prefix += wsum[w];

    const int n_valid = max(prefix - 1, 1);

    // ---- Phase 2: jax.random.uniform(jax.random.key(42), (32,1024)) ----
    // Partitionable threefry-2x32: element j -> lanes (0, j), key (0, 42),
    // output bits = out0 ^ out1.
    const int e = q * TPB + t;                     // emb index 0..1023
    const unsigned j = (unsigned)(b * HIDDEN + e);

    const unsigned k0 = 0u;
    const unsigned k1 = 42u;
    const unsigned k2 = k0 ^ k1 ^ 0x1BD11BDAu;

    unsigned x0 = 0u + k0;
    unsigned x1 = j  + k1;

    #define TF_ROUND(r) { x0 += x1; x1 = rotl32(x1, (r)); x1 ^= x0; }
    TF_ROUND(13) TF_ROUND(15) TF_ROUND(26) TF_ROUND(6)
    x0 += k1; x1 += k2 + 1u;
    TF_ROUND(17) TF_ROUND(29) TF_ROUND(16) TF_ROUND(24)
    x0 += k2; x1 += k0 + 2u;
    TF_ROUND(13) TF_ROUND(15) TF_ROUND(26) TF_ROUND(6)
    x0 += k0; x1 += k1 + 3u;
    TF_ROUND(17) TF_ROUND(29) TF_ROUND(16) TF_ROUND(24)
    x0 += k1; x1 += k2 + 4u;
    TF_ROUND(13) TF_ROUND(15) TF_ROUND(26) TF_ROUND(6)
    x0 += k2; x1 += k0 + 5u;
    #undef TF_ROUND

    const unsigned bits = x0 ^ x1;

    // uniform in [0,1): bitcast((bits>>9) | 0x3f800000) - 1.0f (JAX-exact)
    const float u = __fsub_rn(__uint_as_float((bits >> 9) | 0x3f800000u), 1.0f);

    // idx = min(int(u * n_valid), n_valid - 1); f32 RN mul, truncating convert
    int idx = (int)__fmul_rn(u, (float)n_valid);
    idx = min(idx, n_valid - 1);

    // ---- Phase 3: gather ----
    out[(size_t)b * HIDDEN + e] =
        tokens[(size_t)b * SEQ_LEN * HIDDEN + (size_t)idx * HIDDEN + e];
}

extern "C" void kernel_launch(void* const* d_in, const int* in_sizes, int n_in,
                              void* d_out, int out_size) {
    // Defensive input dispatch by element count (tokens = 32*4096*1024).
    const float* tokens;
    const int*   mask;
    if (in_sizes[0] == BS * SEQ_LEN * HIDDEN) {
        tokens = (const float*)d_in[0];
        mask   = (const int*)d_in[1];
    } else {
        tokens = (const float*)d_in[1];
        mask   = (const int*)d_in[0];
    }
    float* out = (float*)d_out;   // (32, 1024) fp32
    (void)n_in; (void)out_size;

    dim3 grid(QUARTERS, BS);
    condensed_embracement_kernel<<<grid, TPB>>>(tokens, mask, out);
}

// round 4
// speedup vs baseline: 1.0337x; 1.0337x over previous
#include <cuda_runtime.h>
#include <cuda_bf16.h>
#include <cstdint>

// Problem constants
#define BS       32
#define SEQ_LEN  4096
#define HIDDEN   1024
#define QSPLIT   8          // CTAs per batch row
#define TPB      128        // threads per CTA (4 warps)
#define NWARP    (TPB / 32)
#define IPT      (SEQ_LEN / (TPB * 4))   // int4 loads per thread = 8

__device__ __forceinline__ unsigned rotl32(unsigned x, int r) {
    return (x << r) | (x >> (32 - r));
}

// grid = (QSPLIT, BS), block = TPB.
// CTA (q, b): computes batch-b prefix redundantly, handles emb [q*128, q*128+128).
__global__ void __launch_bounds__(TPB, 1)
condensed_embracement_kernel(const float* __restrict__ tokens,
                             const int*   __restrict__ mask,
                             float*       __restrict__ out) {
    const int b = blockIdx.y;
    const int q = blockIdx.x;
    const int t = threadIdx.x;

    // ---- Phase 1: prefix = sum of mask row (mask is 1^L 0^(S-L)) ----
    // 4096 ints / 128 threads = 8 int4 per thread, coalesced, MLP=8.
    const int4* m4 = reinterpret_cast<const int4*>(mask + (size_t)b * SEQ_LEN);
    int s = 0;
    #pragma unroll
    for (int i = 0; i < IPT; i++) {
        int4 v = __ldcs(&m4[t + i * TPB]);   // streaming: no L1 reuse
        s += v.x + v.y + v.z + v.w;
    }

    // Warp-level: single REDUX.SUM.
    s = __reduce_add_sync(0xffffffffu, s);

    // Cross-warp: 4 partials; ONE barrier, then every thread sums all 4.
    __shared__ int wsum[NWARP];
    if ((t & 31) == 0) wsum[t >> 5] = s;
    __syncthreads();
    int prefix = 0;
    #pragma unroll
    for (int w = 0; w < NWARP; w++) prefix += wsum[w];

    const int n_valid = max(prefix - 1, 1);

    // ---- Phase 2: jax.random.uniform(jax.random.key(42), (32,1024)) ----
    // Partitionable threefry-2x32: element j -> lanes (0, j), key (0, 42),
    // output bits = out0 ^ out1.  (Independent of the mask; compiler overlaps
    // this with the in-flight mask loads.)
    const int e = q * TPB + t;                     // emb index 0..1023
    const unsigned j = (unsigned)(b * HIDDEN + e);

    const unsigned k0 = 0u;
    const unsigned k1 = 42u;
    const unsigned k2 = k0 ^ k1 ^ 0x1BD11BDAu;

    unsigned x0 = 0u + k0;
    unsigned x1 = j  + k1;

    #define TF_ROUND(r) { x0 += x1; x1 = rotl32(x1, (r)); x1 ^= x0; }
    TF_ROUND(13) TF_ROUND(15) TF_ROUND(26) TF_ROUND(6)
    x0 += k1; x1 += k2 + 1u;
    TF_ROUND(17) TF_ROUND(29) TF_ROUND(16) TF_ROUND(24)
    x0 += k2; x1 += k0 + 2u;
    TF_ROUND(13) TF_ROUND(15) TF_ROUND(26) TF_ROUND(6)
    x0 += k0; x1 += k1 + 3u;
    TF_ROUND(17) TF_ROUND(29) TF_ROUND(16) TF_ROUND(24)
    x0 += k1; x1 += k2 + 4u;
    TF_ROUND(13) TF_ROUND(15) TF_ROUND(26) TF_ROUND(6)
    x0 += k2; x1 += k0 + 5u;
    #undef TF_ROUND

    const unsigned bits = x0 ^ x1;

    // uniform in [0,1): bitcast((bits>>9) | 0x3f800000) - 1.0f (JAX-exact)
    const float u = __fsub_rn(__uint_as_float((bits >> 9) | 0x3f800000u), 1.0f);

    // idx = min(int(u * n_valid), n_valid - 1); f32 RN mul, truncating convert
    int idx = (int)__fmul_rn(u, (float)n_valid);
    idx = min(idx, n_valid - 1);

    // ---- Phase 3: gather (4B from a random row; inherently scattered) ----
    out[(size_t)b * HIDDEN + e] =
        __ldcs(&tokens[(size_t)b * SEQ_LEN * HIDDEN + (size_t)idx * HIDDEN + e]);
}

extern "C" void kernel_launch(void* const* d_in, const int* in_sizes, int n_in,
                              void* d_out, int out_size) {
    // Defensive input dispatch by element count (tokens = 32*4096*1024).
    const float* tokens;
    const int*   mask;
    if (in_sizes[0] == BS * SEQ_LEN * HIDDEN) {
        tokens = (const float*)d_in[0];
        mask   = (const int*)d_in[1];
    } else {
        tokens = (const float*)d_in[1];
        mask   = (const int*)d_in[0];
    }
    float* out = (float*)d_out;   // (32, 1024) fp32
    (void)n_in; (void)out_size;

    dim3 grid(QSPLIT, BS);
    condensed_embracement_kernel<<<grid, TPB>>>(tokens, mask, out);
}